// round 3
// baseline (speedup 1.0000x reference)
#include <cuda_runtime.h>
#include <cuda_bf16.h>
#include <math.h>

#define NN   512
#define PP   (NN*NN)        // 262144 positions
#define F2   32             // 2*F_IN adjacency channels
#define HH   64
#define HFF  64
#define CCLS 10
#define LLAY 3
#define EE   16384
#define BN_EPS 1e-5f

// ---------------- scratch (static device memory; no allocations) ----------------
__device__ float g_A   [(size_t)PP * F2];   // adjacency, position-major [P][32]
__device__ float g_u0  [(size_t)PP * HH];   // ping-pong u, position-major [P][64]
__device__ float g_u1  [(size_t)PP * HH];
__device__ float g_o1  [(size_t)HH * PP];   // channel-major [64][512][512]
__device__ float g_o2  [(size_t)HH * PP];
__device__ float g_mult[(size_t)HH * PP];   // channel-major
__device__ float g_stats[2 * HH];           // sum, sumsq
__device__ float g_trace[HH];
__device__ float g_total[HH];
__device__ float g_acc  [HFF];

__device__ __forceinline__ float* buf(int s) {
    switch (s) {
        case 0: return g_A;
        case 1: return g_u0;
        case 2: return g_u1;
        case 3: return g_o1;
        case 4: return g_o2;
        default: return g_mult;
    }
}

// ---------------- small utility kernels ----------------
__global__ void zero_A_kernel() {
    // zero g_A as float4
    size_t n4 = ((size_t)PP * F2) / 4;
    float4* p = reinterpret_cast<float4*>(g_A);
    for (size_t i = blockIdx.x * blockDim.x + threadIdx.x; i < n4;
         i += (size_t)gridDim.x * blockDim.x)
        p[i] = make_float4(0.f, 0.f, 0.f, 0.f);
}

__global__ void zero_small_kernel() {
    int t = threadIdx.x;
    if (t < 2 * HH) g_stats[t] = 0.f;
    if (t < HH) { g_trace[t] = 0.f; g_total[t] = 0.f; }
}

// scatter-add edges into dense adjacency: A[src,dst,:] += [x[src], x[dst]]
__global__ void scatter_kernel(const float* __restrict__ x, const int* __restrict__ ei) {
    int t = blockIdx.x * blockDim.x + threadIdx.x;
    if (t >= EE * F2) return;
    int e = t >> 5;           // /32
    int c = t & 31;
    int src = ei[e];
    int dst = ei[EE + e];
    float v = (c < 16) ? x[src * 16 + c] : x[dst * 16 + (c - 16)];
    atomicAdd(&g_A[((size_t)src * NN + dst) * F2 + c], v);
}

// ---------------- per-position linear (GEMM: [P x Cin] @ [Cin x 64]) ----------------
// OUT_CM: write channel-major [64][P]; else position-major [P][64].
// CONCAT: channels [0,64) come from g_mult channel-major, [64,CIN) from in_pm.
template <int CIN, bool OUT_CM, bool CONCAT>
__global__ __launch_bounds__(256)
void linear_kernel(int in_sel, const float* __restrict__ W,
                   const float* __restrict__ bias, int out_sel) {
    constexpr int CPM = CONCAT ? (CIN - 64) : CIN;   // position-major channel count
    const float* in_pm = buf(in_sel);
    float* out = buf(out_sel);

    __shared__ float As[16][128];  // [k][p]
    __shared__ float Bs[16][64];   // [k][o]

    const int tid = threadIdx.x;
    const int pm0 = blockIdx.x * 128;
    int tm, tn;
    if (OUT_CM) { tm = (tid & 15) * 8; tn = (tid >> 4) * 4; }
    else        { tm = (tid >> 4) * 8; tn = (tid & 15) * 4; }

    float acc[8][4];
#pragma unroll
    for (int i = 0; i < 8; i++)
#pragma unroll
        for (int j = 0; j < 4; j++) acc[i][j] = 0.f;

    for (int k0 = 0; k0 < CIN; k0 += 16) {
        // ---- load A tile (128 positions x 16 channels) ----
        if (CONCAT && k0 < 64) {
            // channel-major mult: coalesced along p
#pragma unroll
            for (int r = 0; r < 8; r++) {
                int li = tid + 256 * r;           // 0..2047
                int ci = li >> 7;                 // 0..15
                int pf = li & 127;
                As[ci][pf] = g_mult[(size_t)(k0 + ci) * PP + pm0 + pf];
            }
        } else {
            int kbase = CONCAT ? (k0 - 64) : k0;
#pragma unroll
            for (int q = 0; q < 2; q++) {
                int li = tid * 2 + q;             // 0..511 float4s
                int kq = li & 3;
                int pf = li >> 2;                 // 0..127
                float4 v = *reinterpret_cast<const float4*>(
                    in_pm + (size_t)(pm0 + pf) * CPM + kbase + kq * 4);
                As[kq * 4 + 0][pf] = v.x;
                As[kq * 4 + 1][pf] = v.y;
                As[kq * 4 + 2][pf] = v.z;
                As[kq * 4 + 3][pf] = v.w;
            }
        }
        // ---- load W tile (64 outputs x 16 channels), store [k][o] ----
        {
            int kq = tid & 3;
            int of = tid >> 2;                    // 0..63
            float4 v = *reinterpret_cast<const float4*>(W + of * CIN + k0 + kq * 4);
            Bs[kq * 4 + 0][of] = v.x;
            Bs[kq * 4 + 1][of] = v.y;
            Bs[kq * 4 + 2][of] = v.z;
            Bs[kq * 4 + 3][of] = v.w;
        }
        __syncthreads();

#pragma unroll
        for (int k = 0; k < 16; k++) {
            float a[8];
            *reinterpret_cast<float4*>(a)     = *reinterpret_cast<const float4*>(&As[k][tm]);
            *reinterpret_cast<float4*>(a + 4) = *reinterpret_cast<const float4*>(&As[k][tm + 4]);
            float4 b4 = *reinterpret_cast<const float4*>(&Bs[k][tn]);
            float b[4] = { b4.x, b4.y, b4.z, b4.w };
#pragma unroll
            for (int i = 0; i < 8; i++)
#pragma unroll
                for (int j = 0; j < 4; j++) acc[i][j] += a[i] * b[j];
        }
        __syncthreads();
    }

    // ---- epilogue ----
    if (OUT_CM) {
#pragma unroll
        for (int j = 0; j < 4; j++) {
            int o = tn + j;
            float bv = bias[o];
            float4 v0 = make_float4(acc[0][j] + bv, acc[1][j] + bv,
                                    acc[2][j] + bv, acc[3][j] + bv);
            float4 v1 = make_float4(acc[4][j] + bv, acc[5][j] + bv,
                                    acc[6][j] + bv, acc[7][j] + bv);
            *reinterpret_cast<float4*>(out + (size_t)o * PP + pm0 + tm)     = v0;
            *reinterpret_cast<float4*>(out + (size_t)o * PP + pm0 + tm + 4) = v1;
        }
    } else {
        float b0 = bias[tn], b1 = bias[tn + 1], b2 = bias[tn + 2], b3 = bias[tn + 3];
#pragma unroll
        for (int i = 0; i < 8; i++) {
            int p = pm0 + tm + i;
            float4 v = make_float4(acc[i][0] + b0, acc[i][1] + b1,
                                   acc[i][2] + b2, acc[i][3] + b3);
            *reinterpret_cast<float4*>(out + (size_t)p * HH + tn) = v;
        }
    }
}

// ---------------- batched 512x512x512 SGEMM per channel ----------------
// mult[h] = o1[h] @ o2[h], all row-major [512][512], channel-major storage.
__global__ __launch_bounds__(256)
void bgemm_kernel() {
    const int h = blockIdx.z;
    const float* __restrict__ Ah = g_o1 + (size_t)h * PP;
    const float* __restrict__ Bh = g_o2 + (size_t)h * PP;
    float* __restrict__ Ch = g_mult + (size_t)h * PP;

    __shared__ float As[8][128];  // transposed A tile [k][m]
    __shared__ float Bs[8][128];  // [k][n]

    const int tid = threadIdx.x;
    const int bm = blockIdx.y * 128;
    const int bn = blockIdx.x * 128;
    const int tm = (tid >> 4) * 8;
    const int tn = (tid & 15) * 8;

    const int arow = tid >> 1;            // 0..127
    const int acol = (tid & 1) * 4;       // 0 or 4
    const int brow = tid >> 5;            // 0..7
    const int bcol = (tid & 31) * 4;      // 0..124

    float acc[8][8];
#pragma unroll
    for (int i = 0; i < 8; i++)
#pragma unroll
        for (int j = 0; j < 8; j++) acc[i][j] = 0.f;

    for (int k0 = 0; k0 < NN; k0 += 8) {
        float4 av = *reinterpret_cast<const float4*>(Ah + (size_t)(bm + arow) * NN + k0 + acol);
        As[acol + 0][arow] = av.x;
        As[acol + 1][arow] = av.y;
        As[acol + 2][arow] = av.z;
        As[acol + 3][arow] = av.w;
        *reinterpret_cast<float4*>(&Bs[brow][bcol]) =
            *reinterpret_cast<const float4*>(Bh + (size_t)(k0 + brow) * NN + bn + bcol);
        __syncthreads();

#pragma unroll
        for (int k = 0; k < 8; k++) {
            float a[8], b[8];
            *reinterpret_cast<float4*>(a)     = *reinterpret_cast<const float4*>(&As[k][tm]);
            *reinterpret_cast<float4*>(a + 4) = *reinterpret_cast<const float4*>(&As[k][tm + 4]);
            *reinterpret_cast<float4*>(b)     = *reinterpret_cast<const float4*>(&Bs[k][tn]);
            *reinterpret_cast<float4*>(b + 4) = *reinterpret_cast<const float4*>(&Bs[k][tn + 4]);
#pragma unroll
            for (int i = 0; i < 8; i++)
#pragma unroll
                for (int j = 0; j < 8; j++) acc[i][j] += a[i] * b[j];
        }
        __syncthreads();
    }

#pragma unroll
    for (int i = 0; i < 8; i++) {
        float4 v0 = make_float4(acc[i][0], acc[i][1], acc[i][2], acc[i][3]);
        float4 v1 = make_float4(acc[i][4], acc[i][5], acc[i][6], acc[i][7]);
        *reinterpret_cast<float4*>(Ch + (size_t)(bm + tm + i) * NN + bn + tn)     = v0;
        *reinterpret_cast<float4*>(Ch + (size_t)(bm + tm + i) * NN + bn + tn + 4) = v1;
    }
}

// ---------------- batchnorm (training-mode stats over all P positions) ----------------
__global__ void bn_reduce_kernel(int sel) {
    const float* u = buf(sel);
    int c = threadIdx.x & 63;
    int pr = threadIdx.x >> 6;  // 0..3
    float s = 0.f, sq = 0.f;
    for (int p = blockIdx.x * 4 + pr; p < PP; p += gridDim.x * 4) {
        float v = u[(size_t)p * HH + c];
        s += v;
        sq += v * v;
    }
    atomicAdd(&g_stats[c], s);
    atomicAdd(&g_stats[HH + c], sq);
}

__global__ void bn_norm_kernel(int sel, const float* __restrict__ gam,
                               const float* __restrict__ bet) {
    float* u = buf(sel);
    const float invP = 1.f / (float)PP;
    size_t n = (size_t)PP * HH;
    for (size_t i = (size_t)blockIdx.x * blockDim.x + threadIdx.x; i < n;
         i += (size_t)gridDim.x * blockDim.x) {
        int c = (int)(i & 63);
        float m = g_stats[c] * invP;
        float var = g_stats[HH + c] * invP - m * m;
        u[i] = (u[i] - m) * rsqrtf(var + BN_EPS) * gam[c] + bet[c];
    }
}

// ---------------- trace + total per channel ----------------
__global__ void trace_total_kernel(int sel, int cin) {
    const float* u = buf(sel);
    int c = threadIdx.x % cin;
    int per = 256 / cin;
    int pr = threadIdx.x / cin;
    float tot = 0.f, tr = 0.f;
    for (int p = blockIdx.x * per + pr; p < PP; p += gridDim.x * per) {
        float v = u[(size_t)p * cin + c];
        tot += v;
        if (p % (NN + 1) == 0) tr += v;   // diagonal: p = i*(N+1)
    }
    atomicAdd(&g_total[c], tot);
    atomicAdd(&g_trace[c], tr);
}

// ---------------- graph-level feature extractor ----------------
__global__ void extractor_kernel(const float* __restrict__ w1, const float* __restrict__ b1,
                                 const float* __restrict__ w2, const float* __restrict__ w3,
                                 int cin, int init) {
    __shared__ float s_out[HFF];
    int o = threadIdx.x;  // 64 threads
    const float inv_n = 1.f / (float)NN;
    const float inv_od = 1.f / ((float)NN * (float)(NN - 1));
    float v = b1[o];
    for (int c = 0; c < cin; c++) {
        v += (g_trace[c] * inv_n) * w1[o * cin + c];
        v += ((g_total[c] - g_trace[c]) * inv_od) * w2[o * cin + c];
    }
    s_out[o] = v;
    __syncthreads();
    float t = 0.f;
    for (int j = 0; j < HFF; j++) t += fmaxf(s_out[j], 0.f) * w3[o * HFF + j];
    v += t;
    if (init) g_acc[o] = v;
    else      g_acc[o] += v;
}

// ---------------- final head: relu/L, after_conv, final linear, log_softmax ----------------
__global__ void final_kernel(const float* __restrict__ acw, const float* __restrict__ acb,
                             const float* __restrict__ flw, const float* __restrict__ flb,
                             float* __restrict__ out) {
    __shared__ float t[HFF], h2[HFF], lg[CCLS];
    int o = threadIdx.x;
    t[o] = fmaxf(g_acc[o], 0.f) * (1.f / (float)LLAY);
    __syncthreads();
    float v = acb[o];
    for (int j = 0; j < HFF; j++) v += t[j] * acw[o * HFF + j];
    h2[o] = t[o] + fmaxf(v, 0.f);
    __syncthreads();
    if (o < CCLS) {
        float s = flb[o];
        for (int j = 0; j < HFF; j++) s += h2[j] * flw[o * HFF + j];
        lg[o] = s;
    }
    __syncthreads();
    if (o < CCLS) {
        float m = -1e30f;
        for (int j = 0; j < CCLS; j++) m = fmaxf(m, lg[j]);
        float se = 0.f;
        for (int j = 0; j < CCLS; j++) se += expf(lg[j] - m);
        out[o] = lg[o] - m - logf(se);
    }
}

// ---------------- launcher ----------------
extern "C" void kernel_launch(void* const* d_in, const int* in_sizes, int n_in,
                              void* d_out, int out_size) {
    const float* x      = (const float*)d_in[0];
    const int*   ei     = (const int*)  d_in[1];
    const float* np1_w  = (const float*)d_in[2];
    const float* np1_b  = (const float*)d_in[3];
    const float* np2_w  = (const float*)d_in[4];
    const float* np3_w  = (const float*)d_in[5];
    const float* c0_m1w = (const float*)d_in[6];
    const float* c0_m1b = (const float*)d_in[7];
    const float* c0_m2w = (const float*)d_in[8];
    const float* c0_m2b = (const float*)d_in[9];
    const float* c0_m4w = (const float*)d_in[10];
    const float* c0_m4b = (const float*)d_in[11];
    const float* cm1_w  = (const float*)d_in[12];
    const float* cm1_b  = (const float*)d_in[13];
    const float* cm2_w  = (const float*)d_in[14];
    const float* cm2_b  = (const float*)d_in[15];
    const float* cm4_w  = (const float*)d_in[16];
    const float* cm4_b  = (const float*)d_in[17];
    const float* bn_g   = (const float*)d_in[18];
    const float* bn_b   = (const float*)d_in[19];
    const float* fe1_w  = (const float*)d_in[20];
    const float* fe1_b  = (const float*)d_in[21];
    const float* fe2_w  = (const float*)d_in[22];
    const float* fe3_w  = (const float*)d_in[23];
    const float* ac_w   = (const float*)d_in[24];
    const float* ac_b   = (const float*)d_in[25];
    const float* fl_w   = (const float*)d_in[26];
    const float* fl_b   = (const float*)d_in[27];

    // Build dense adjacency
    zero_A_kernel<<<2048, 256>>>();
    scatter_kernel<<<(EE * F2) / 256, 256>>>(x, ei);

    // no_prop extractor on A
    zero_small_kernel<<<1, 128>>>();
    trace_total_kernel<<<256, 256>>>(0, F2);
    extractor_kernel<<<1, 64>>>(np1_w, np1_b, np2_w, np3_w, F2, 1);

    for (int l = 0; l < LLAY; l++) {
        int insel  = (l == 0) ? 0 : ((l == 1) ? 1 : 2);
        int outsel = (l == 0) ? 1 : ((l == 1) ? 2 : 1);
        const float *m1w, *m1b, *m2w, *m2b, *m4w, *m4b;
        if (l == 0) {
            m1w = c0_m1w; m1b = c0_m1b; m2w = c0_m2w; m2b = c0_m2b;
            m4w = c0_m4w; m4b = c0_m4b;
        } else {
            m1w = cm1_w + (size_t)(l - 1) * HH * HH;
            m1b = cm1_b + (size_t)(l - 1) * HH;
            m2w = cm2_w + (size_t)(l - 1) * HH * HH;
            m2b = cm2_b + (size_t)(l - 1) * HH;
            m4w = cm4_w + (size_t)(l - 1) * HH * 2 * HH;
            m4b = cm4_b + (size_t)(l - 1) * HH;
        }

        if (l == 0) {
            linear_kernel<32, true, false><<<PP / 128, 256>>>(insel, m1w, m1b, 3);
            linear_kernel<32, true, false><<<PP / 128, 256>>>(insel, m2w, m2b, 4);
        } else {
            linear_kernel<64, true, false><<<PP / 128, 256>>>(insel, m1w, m1b, 3);
            linear_kernel<64, true, false><<<PP / 128, 256>>>(insel, m2w, m2b, 4);
        }

        bgemm_kernel<<<dim3(4, 4, 64), 256>>>();

        if (l == 0) linear_kernel<96,  false, true><<<PP / 128, 256>>>(insel, m4w, m4b, outsel);
        else        linear_kernel<128, false, true><<<PP / 128, 256>>>(insel, m4w, m4b, outsel);

        zero_small_kernel<<<1, 128>>>();
        bn_reduce_kernel<<<512, 256>>>(outsel);
        bn_norm_kernel<<<8192, 256>>>(outsel, bn_g + l * HH, bn_b + l * HH);
        trace_total_kernel<<<256, 256>>>(outsel, HH);
        extractor_kernel<<<1, 64>>>(fe1_w + (size_t)l * HFF * HH, fe1_b + (size_t)l * HFF,
                                    fe2_w + (size_t)l * HFF * HH, fe3_w + (size_t)l * HFF * HFF,
                                    HH, 0);
    }

    final_kernel<<<1, 64>>>(ac_w, ac_b, fl_w, fl_b, (float*)d_out);
}

// round 6
// speedup vs baseline: 1.9418x; 1.9418x over previous
#include <cuda_runtime.h>
#include <cuda_bf16.h>
#include <math.h>
#include <stdint.h>

#define NN   512
#define PP   (NN*NN)
#define F2   32
#define HH   64
#define HFF  64
#define CCLS 10
#define LLAY 3
#define EE   16384
#define BN_EPS 1e-5f

// ---------------- scratch (static device memory; no allocations) ----------------
__device__ float g_A   [(size_t)PP * F2];     // adjacency, position-major [P][32]
__device__ float g_u0  [(size_t)PP * HH];     // ping-pong u (pre-bn), position-major
__device__ float g_u1  [(size_t)PP * HH];
__device__ float g_mult[(size_t)HH * PP];     // channel-major [64][512][512] fp32
__device__ __nv_bfloat16 g_o1h[(size_t)HH * PP];  // channel-major bf16 splits
__device__ __nv_bfloat16 g_o1l[(size_t)HH * PP];
__device__ __nv_bfloat16 g_o2h[(size_t)HH * PP];
__device__ __nv_bfloat16 g_o2l[(size_t)HH * PP];
__device__ float g_stats[HH];                 // sumsq
__device__ float g_trace[HH];
__device__ float g_total[HH];                 // == sum
__device__ float g_acc  [HFF];
__device__ float g_scale[HH], g_shift[HH];
__device__ float g_w1a[HH*HH], g_b1a[HH];
__device__ float g_w2a[HH*HH], g_b2a[HH];
__device__ float g_w4a[HH*2*HH], g_b4a[HH];

__device__ __forceinline__ float* buf(int s) {
    switch (s) {
        case 0: return g_A;
        case 1: return g_u0;
        default: return g_u1;
    }
}

// ---------------- PTX helpers (all portable to compute_103) ----------------
__device__ __forceinline__ uint32_t smem_to_u32(const void* p) {
    uint32_t a;
    asm("{ .reg .u64 t; cvta.to.shared.u64 t, %1; cvt.u32.u64 %0, t; }" : "=r"(a) : "l"(p));
    return a;
}
#define CP_ASYNC16(dst, src) \
    asm volatile("cp.async.cg.shared.global [%0], [%1], 16;" :: "r"(dst), "l"(src))
#define CP_COMMIT() asm volatile("cp.async.commit_group;" ::: "memory")
#define CP_WAIT0()  asm volatile("cp.async.wait_group 0;" ::: "memory")
#define CP_WAIT1()  asm volatile("cp.async.wait_group 1;" ::: "memory")

__device__ __forceinline__ void ldmA(uint32_t* r, uint32_t addr) {
    asm volatile("ldmatrix.sync.aligned.m8n8.x4.shared.b16 {%0,%1,%2,%3}, [%4];"
        : "=r"(r[0]), "=r"(r[1]), "=r"(r[2]), "=r"(r[3]) : "r"(addr));
}
__device__ __forceinline__ void ldmBt(uint32_t* r, uint32_t addr) {
    asm volatile("ldmatrix.sync.aligned.m8n8.x2.trans.shared.b16 {%0,%1}, [%2];"
        : "=r"(r[0]), "=r"(r[1]) : "r"(addr));
}
__device__ __forceinline__ void mma16816(float* c, const uint32_t* a, const uint32_t* b) {
    asm volatile("mma.sync.aligned.m16n8k16.row.col.f32.bf16.bf16.f32 "
        "{%0,%1,%2,%3}, {%4,%5,%6,%7}, {%8,%9}, {%0,%1,%2,%3};"
        : "+f"(c[0]), "+f"(c[1]), "+f"(c[2]), "+f"(c[3])
        : "r"(a[0]), "r"(a[1]), "r"(a[2]), "r"(a[3]), "r"(b[0]), "r"(b[1]));
}

// ---------------- small utility kernels ----------------
__global__ void zero_A_kernel() {
    size_t n4 = ((size_t)PP * F2) / 4;
    float4* p = reinterpret_cast<float4*>(g_A);
    for (size_t i = blockIdx.x * blockDim.x + threadIdx.x; i < n4;
         i += (size_t)gridDim.x * blockDim.x)
        p[i] = make_float4(0.f, 0.f, 0.f, 0.f);
}
__global__ void zero_small_kernel() {
    int t = threadIdx.x;
    if (t < HH) { g_stats[t] = 0.f; g_trace[t] = 0.f; g_total[t] = 0.f; }
}
__global__ void scatter_kernel(const float* __restrict__ x, const int* __restrict__ ei) {
    int t = blockIdx.x * blockDim.x + threadIdx.x;
    if (t >= EE * F2) return;
    int e = t >> 5;
    int c = t & 31;
    int src = ei[e];
    int dst = ei[EE + e];
    float v = (c < 16) ? x[src * 16 + c] : x[dst * 16 + (c - 16)];
    atomicAdd(&g_A[((size_t)src * NN + dst) * F2 + c], v);
}

// ---------------- per-position linear (GEMM: [P x Cin] @ [Cin x 64]) ----------------
template <int CIN, bool OUT_CM, bool CONCAT>
__global__ __launch_bounds__(256)
void linear_kernel(int in_sel, const float* __restrict__ Wext,
                   const float* __restrict__ bext, int wsel, int outsel) {
    constexpr int CPM = CONCAT ? (CIN - 64) : CIN;
    const float* in_pm = buf(in_sel);
    const float* W    = (wsel == 1) ? g_w1a : (wsel == 2) ? g_w2a : (wsel == 4) ? g_w4a : Wext;
    const float* bias = (wsel == 1) ? g_b1a : (wsel == 2) ? g_b2a : (wsel == 4) ? g_b4a : bext;

    __shared__ float As[16][128];
    __shared__ float Bs[16][64];

    const int tid = threadIdx.x;
    const int pm0 = blockIdx.x * 128;
    int tm, tn;
    if (OUT_CM) { tm = (tid & 15) * 8; tn = (tid >> 4) * 4; }
    else        { tm = (tid >> 4) * 8; tn = (tid & 15) * 4; }

    float acc[8][4];
#pragma unroll
    for (int i = 0; i < 8; i++)
#pragma unroll
        for (int j = 0; j < 4; j++) acc[i][j] = 0.f;

    for (int k0 = 0; k0 < CIN; k0 += 16) {
        if (CONCAT && k0 < 64) {
#pragma unroll
            for (int r = 0; r < 8; r++) {
                int li = tid + 256 * r;
                int ci = li >> 7;
                int pf = li & 127;
                As[ci][pf] = g_mult[(size_t)(k0 + ci) * PP + pm0 + pf];
            }
        } else {
            int kbase = CONCAT ? (k0 - 64) : k0;
#pragma unroll
            for (int q = 0; q < 2; q++) {
                int li = tid * 2 + q;
                int kq = li & 3;
                int pf = li >> 2;
                float4 v = *reinterpret_cast<const float4*>(
                    in_pm + (size_t)(pm0 + pf) * CPM + kbase + kq * 4);
                As[kq * 4 + 0][pf] = v.x;
                As[kq * 4 + 1][pf] = v.y;
                As[kq * 4 + 2][pf] = v.z;
                As[kq * 4 + 3][pf] = v.w;
            }
        }
        {
            int kq = tid & 3;
            int of = tid >> 2;
            float4 v = *reinterpret_cast<const float4*>(W + of * CIN + k0 + kq * 4);
            Bs[kq * 4 + 0][of] = v.x;
            Bs[kq * 4 + 1][of] = v.y;
            Bs[kq * 4 + 2][of] = v.z;
            Bs[kq * 4 + 3][of] = v.w;
        }
        __syncthreads();

#pragma unroll
        for (int k = 0; k < 16; k++) {
            float a[8];
            *reinterpret_cast<float4*>(a)     = *reinterpret_cast<const float4*>(&As[k][tm]);
            *reinterpret_cast<float4*>(a + 4) = *reinterpret_cast<const float4*>(&As[k][tm + 4]);
            float4 b4 = *reinterpret_cast<const float4*>(&Bs[k][tn]);
            float b[4] = { b4.x, b4.y, b4.z, b4.w };
#pragma unroll
            for (int i = 0; i < 8; i++)
#pragma unroll
                for (int j = 0; j < 4; j++) acc[i][j] += a[i] * b[j];
        }
        __syncthreads();
    }

    if (OUT_CM) {
        // write bf16 hi/lo split, channel-major, for mma bgemm
        __nv_bfloat16* oh = (outsel == 1) ? g_o1h : g_o2h;
        __nv_bfloat16* ol = (outsel == 1) ? g_o1l : g_o2l;
#pragma unroll
        for (int j = 0; j < 4; j++) {
            int o = tn + j;
            float bv = bias[o];
            __nv_bfloat16 hi[8], lo[8];
#pragma unroll
            for (int i = 0; i < 8; i++) {
                float v = acc[i][j] + bv;
                __nv_bfloat16 h = __float2bfloat16(v);
                hi[i] = h;
                lo[i] = __float2bfloat16(v - __bfloat162float(h));
            }
            *reinterpret_cast<uint4*>(oh + (size_t)o * PP + pm0 + tm) =
                *reinterpret_cast<const uint4*>(hi);
            *reinterpret_cast<uint4*>(ol + (size_t)o * PP + pm0 + tm) =
                *reinterpret_cast<const uint4*>(lo);
        }
    } else {
        float* out = buf(outsel);
        float b0 = bias[tn], b1 = bias[tn + 1], b2 = bias[tn + 2], b3 = bias[tn + 3];
#pragma unroll
        for (int i = 0; i < 8; i++) {
            int p = pm0 + tm + i;
            float4 v = make_float4(acc[i][0] + b0, acc[i][1] + b1,
                                   acc[i][2] + b2, acc[i][3] + b3);
            *reinterpret_cast<float4*>(out + (size_t)p * HH + tn) = v;
        }
    }
}

// ---------------- mma.sync batched GEMM: mult[h] = o1[h] @ o2[h] (bf16x3) ----------------
// CTA: 128x128 tile of channel h, 256 threads = 8 warps (2 m-rows x 4 n-cols),
// warp tile 64x32 (4x4 m16n8 fragments). K-chunk 64, 2-stage cp.async pipeline.
// SMEM per stage: Ah(16K) Al(16K) Bh(16K) Bl(16K) = 64KB; 2 stages = 128KB dynamic.
#define BGM_STAGE 65536
#define BGM_SMEM  (2 * BGM_STAGE)
// A tile: [128 m][64 k] bf16, row 128B, swizzle: chunk(k/8) ^= (m&7)
// B tile: [64 k][128 n] bf16, row 256B, swizzle: chunk(n/8) ^= (k&7)  (per-row 16 chunks)

__device__ __forceinline__ void bgm_load_stage(int k0, uint32_t sb, int h, int m0, int n0) {
    const int tid = threadIdx.x;
    const size_t hoff = (size_t)h << 18;
    // A: 2048 16B-chunks (2 halves x 128 rows x 8 chunks)
#pragma unroll
    for (int it = 0; it < 8; it++) {
        int idx = tid + it * 256;
        int half = idx >> 10;
        int r = (idx >> 3) & 127;
        int c = idx & 7;
        const __nv_bfloat16* src = (half ? g_o1l : g_o1h) + hoff + (size_t)(m0 + r) * NN + k0 + c * 8;
        uint32_t dst = sb + half * 16384 + r * 128 + (((uint32_t)(c ^ (r & 7))) << 4);
        CP_ASYNC16(dst, (uint64_t)__cvta_generic_to_global(src));
    }
    // B: 2048 16B-chunks (2 halves x 64 k-rows x 16 chunks)
#pragma unroll
    for (int it = 0; it < 8; it++) {
        int idx = tid + it * 256;
        int half = idx >> 10;
        int k = (idx >> 4) & 63;
        int c = idx & 15;
        const __nv_bfloat16* src = (half ? g_o2l : g_o2h) + hoff + (size_t)(k0 + k) * NN + n0 + c * 8;
        uint32_t dst = sb + 32768 + half * 16384 + k * 256 + (((uint32_t)(c ^ (k & 7))) << 4);
        CP_ASYNC16(dst, (uint64_t)__cvta_generic_to_global(src));
    }
}

__global__ __launch_bounds__(256, 1)
void bgemm_mma_kernel() {
    extern __shared__ char smem[];
    const uint32_t sbase = smem_to_u32(smem);
    const int tid = threadIdx.x;
    const int lane = tid & 31;
    const int w = tid >> 5;
    const int wm = w & 1;        // 2 warp-rows
    const int wn = w >> 1;       // 4 warp-cols
    const int m0w = wm * 64;
    const int n0w = wn * 32;
    const int h  = blockIdx.z;
    const int m0 = blockIdx.y * 128;
    const int n0 = blockIdx.x * 128;

    // ldmatrix lane address components
    const int a_row_lane = (lane & 7) + ((lane >> 3) & 1) * 8;  // 0..15
    const int a_k_lane   = lane >> 4;                           // 0/1 (k-chunk offset)
    const int b_k_lane   = lane & 15;

    float acc[4][4][4];
#pragma unroll
    for (int i = 0; i < 4; i++)
#pragma unroll
        for (int j = 0; j < 4; j++)
#pragma unroll
            for (int q = 0; q < 4; q++) acc[i][j][q] = 0.f;

    bgm_load_stage(0, sbase, h, m0, n0);
    CP_COMMIT();

    const int NK = NN / 64;  // 8
    for (int kc = 0; kc < NK; kc++) {
        if (kc + 1 < NK) {
            bgm_load_stage((kc + 1) * 64, sbase + ((kc + 1) & 1) * BGM_STAGE, h, m0, n0);
            CP_COMMIT();
            CP_WAIT1();
        } else {
            CP_WAIT0();
        }
        __syncthreads();

        const uint32_t sA = sbase + (kc & 1) * BGM_STAGE;
        const uint32_t sB = sA + 32768;
#pragma unroll
        for (int ks = 0; ks < 4; ks++) {
            uint32_t Ah[4][4], Al[4][4], Bh[4][2], Bl[4][2];
#pragma unroll
            for (int mt = 0; mt < 4; mt++) {
                int row = m0w + mt * 16 + a_row_lane;
                int kchunk = ks * 2 + a_k_lane;
                uint32_t off = row * 128 + (((uint32_t)(kchunk ^ (row & 7))) << 4);
                ldmA(Ah[mt], sA + off);
                ldmA(Al[mt], sA + 16384 + off);
            }
            {
                int kk = ks * 16 + b_k_lane;
                int kx = kk & 7;
#pragma unroll
                for (int nt = 0; nt < 4; nt++) {
                    int nchunk = wn * 4 + nt;
                    uint32_t off = kk * 256 + (((uint32_t)(nchunk ^ kx)) << 4);
                    ldmBt(Bh[nt], sB + off);
                    ldmBt(Bl[nt], sB + 16384 + off);
                }
            }
#pragma unroll
            for (int mt = 0; mt < 4; mt++)
#pragma unroll
                for (int nt = 0; nt < 4; nt++) {
                    mma16816(acc[mt][nt], Ah[mt], Bh[nt]);
                    mma16816(acc[mt][nt], Ah[mt], Bl[nt]);
                    mma16816(acc[mt][nt], Al[mt], Bh[nt]);
                }
        }
        __syncthreads();
    }

    // epilogue: fragments -> g_mult fp32 channel-major [h][m][n]
    float* base = g_mult + ((size_t)h << 18);
    const int rq = lane >> 2;          // 0..7
    const int cq = (lane & 3) * 2;     // 0,2,4,6
#pragma unroll
    for (int mt = 0; mt < 4; mt++) {
#pragma unroll
        for (int nt = 0; nt < 4; nt++) {
            int row = m0 + m0w + mt * 16 + rq;
            int col = n0 + n0w + nt * 8 + cq;
            float* d0 = base + (size_t)row * NN + col;
            *reinterpret_cast<float2*>(d0)            = make_float2(acc[mt][nt][0], acc[mt][nt][1]);
            *reinterpret_cast<float2*>(d0 + 8 * NN)   = make_float2(acc[mt][nt][2], acc[mt][nt][3]);
        }
    }
}

// ---------------- fused reduction: sum, sumsq, trace (pre-bn) ----------------
template <int CIN, bool STATS>
__global__ __launch_bounds__(256)
void reduce_kernel(int sel) {
    const float* u = buf(sel);
    constexpr int QUADS = CIN / 4;
    constexpr int RG = 256 / QUADS;
    const int q = threadIdx.x % QUADS;
    const int rg = threadIdx.x / QUADS;
    float t0 = 0, t1 = 0, t2 = 0, t3 = 0;
    float s0 = 0, s1 = 0, s2 = 0, s3 = 0;
    float r0 = 0, r1 = 0, r2 = 0, r3 = 0;
    for (int p = blockIdx.x * RG + rg; p < PP; p += gridDim.x * RG) {
        float4 v = *reinterpret_cast<const float4*>(u + (size_t)p * CIN + q * 4);
        t0 += v.x; t1 += v.y; t2 += v.z; t3 += v.w;
        if (STATS) { s0 += v.x * v.x; s1 += v.y * v.y; s2 += v.z * v.z; s3 += v.w * v.w; }
        if (p % (NN + 1) == 0) { r0 += v.x; r1 += v.y; r2 += v.z; r3 += v.w; }
    }
    __shared__ float st[CIN], ss[CIN], sr[CIN];
    if (threadIdx.x < CIN) { st[threadIdx.x] = 0.f; ss[threadIdx.x] = 0.f; sr[threadIdx.x] = 0.f; }
    __syncthreads();
    atomicAdd(&st[q * 4 + 0], t0); atomicAdd(&st[q * 4 + 1], t1);
    atomicAdd(&st[q * 4 + 2], t2); atomicAdd(&st[q * 4 + 3], t3);
    atomicAdd(&sr[q * 4 + 0], r0); atomicAdd(&sr[q * 4 + 1], r1);
    atomicAdd(&sr[q * 4 + 2], r2); atomicAdd(&sr[q * 4 + 3], r3);
    if (STATS) {
        atomicAdd(&ss[q * 4 + 0], s0); atomicAdd(&ss[q * 4 + 1], s1);
        atomicAdd(&ss[q * 4 + 2], s2); atomicAdd(&ss[q * 4 + 3], s3);
    }
    __syncthreads();
    if (threadIdx.x < CIN) {
        atomicAdd(&g_total[threadIdx.x], st[threadIdx.x]);
        atomicAdd(&g_trace[threadIdx.x], sr[threadIdx.x]);
        if (STATS) atomicAdd(&g_stats[threadIdx.x], ss[threadIdx.x]);
    }
}

// bn finalize: compute scale/shift; transform trace/total to post-bn analytically
__global__ void finalize_kernel(const float* __restrict__ g, const float* __restrict__ b) {
    int c = threadIdx.x;  // 64
    float sum = g_total[c], sumsq = g_stats[c], tr = g_trace[c];
    float m = sum * (1.f / (float)PP);
    float var = sumsq * (1.f / (float)PP) - m * m;
    float sc = g[c] * rsqrtf(var + BN_EPS);
    float sh = b[c] - m * sc;
    g_scale[c] = sc;
    g_shift[c] = sh;
    g_trace[c] = tr * sc + sh * (float)NN;
    g_total[c] = sum * sc + sh * (float)PP;
}

// fold bn affine into next layer's m1/m2/m4 weights
__global__ void adjust_kernel(const float* __restrict__ w1, const float* __restrict__ b1,
                              const float* __restrict__ w2, const float* __restrict__ b2,
                              const float* __restrict__ w4, const float* __restrict__ b4) {
    int o = threadIdx.x;  // 64
    float a1 = b1[o], a2 = b2[o], a4 = b4[o];
    for (int c = 0; c < HH; c++) {
        float sc = g_scale[c], sh = g_shift[c];
        float w = w1[o * HH + c];
        g_w1a[o * HH + c] = w * sc; a1 += w * sh;
        w = w2[o * HH + c];
        g_w2a[o * HH + c] = w * sc; a2 += w * sh;
        g_w4a[o * 2 * HH + c] = w4[o * 2 * HH + c];      // mult columns unchanged
        w = w4[o * 2 * HH + HH + c];
        g_w4a[o * 2 * HH + HH + c] = w * sc; a4 += w * sh;
    }
    g_b1a[o] = a1; g_b2a[o] = a2; g_b4a[o] = a4;
}

// ---------------- graph-level feature extractor ----------------
__global__ void extractor_kernel(const float* __restrict__ w1, const float* __restrict__ b1,
                                 const float* __restrict__ w2, const float* __restrict__ w3,
                                 int cin, int init) {
    __shared__ float s_out[HFF];
    int o = threadIdx.x;  // 64
    const float inv_n = 1.f / (float)NN;
    const float inv_od = 1.f / ((float)NN * (float)(NN - 1));
    float v = b1[o];
    for (int c = 0; c < cin; c++) {
        v += (g_trace[c] * inv_n) * w1[o * cin + c];
        v += ((g_total[c] - g_trace[c]) * inv_od) * w2[o * cin + c];
    }
    s_out[o] = v;
    __syncthreads();
    float t = 0.f;
    for (int j = 0; j < HFF; j++) t += fmaxf(s_out[j], 0.f) * w3[o * HFF + j];
    v += t;
    if (init) g_acc[o] = v;
    else      g_acc[o] += v;
}

// ---------------- final head ----------------
__global__ void final_kernel(const float* __restrict__ acw, const float* __restrict__ acb,
                             const float* __restrict__ flw, const float* __restrict__ flb,
                             float* __restrict__ out) {
    __shared__ float t[HFF], h2[HFF], lg[CCLS];
    int o = threadIdx.x;
    t[o] = fmaxf(g_acc[o], 0.f) * (1.f / (float)LLAY);
    __syncthreads();
    float v = acb[o];
    for (int j = 0; j < HFF; j++) v += t[j] * acw[o * HFF + j];
    h2[o] = t[o] + fmaxf(v, 0.f);
    __syncthreads();
    if (o < CCLS) {
        float s = flb[o];
        for (int j = 0; j < HFF; j++) s += h2[j] * flw[o * HFF + j];
        lg[o] = s;
    }
    __syncthreads();
    if (o < CCLS) {
        float m = -1e30f;
        for (int j = 0; j < CCLS; j++) m = fmaxf(m, lg[j]);
        float se = 0.f;
        for (int j = 0; j < CCLS; j++) se += expf(lg[j] - m);
        out[o] = lg[o] - m - logf(se);
    }
}

// ---------------- launcher ----------------
extern "C" void kernel_launch(void* const* d_in, const int* in_sizes, int n_in,
                              void* d_out, int out_size) {
    const float* x      = (const float*)d_in[0];
    const int*   ei     = (const int*)  d_in[1];
    const float* np1_w  = (const float*)d_in[2];
    const float* np1_b  = (const float*)d_in[3];
    const float* np2_w  = (const float*)d_in[4];
    const float* np3_w  = (const float*)d_in[5];
    const float* c0_m1w = (const float*)d_in[6];
    const float* c0_m1b = (const float*)d_in[7];
    const float* c0_m2w = (const float*)d_in[8];
    const float* c0_m2b = (const float*)d_in[9];
    const float* c0_m4w = (const float*)d_in[10];
    const float* c0_m4b = (const float*)d_in[11];
    const float* cm1_w  = (const float*)d_in[12];
    const float* cm1_b  = (const float*)d_in[13];
    const float* cm2_w  = (const float*)d_in[14];
    const float* cm2_b  = (const float*)d_in[15];
    const float* cm4_w  = (const float*)d_in[16];
    const float* cm4_b  = (const float*)d_in[17];
    const float* bn_g   = (const float*)d_in[18];
    const float* bn_b   = (const float*)d_in[19];
    const float* fe1_w  = (const float*)d_in[20];
    const float* fe1_b  = (const float*)d_in[21];
    const float* fe2_w  = (const float*)d_in[22];
    const float* fe3_w  = (const float*)d_in[23];
    const float* ac_w   = (const float*)d_in[24];
    const float* ac_b   = (const float*)d_in[25];
    const float* fl_w   = (const float*)d_in[26];
    const float* fl_b   = (const float*)d_in[27];

    cudaFuncSetAttribute(bgemm_mma_kernel, cudaFuncAttributeMaxDynamicSharedMemorySize, BGM_SMEM);

    // Build dense adjacency
    zero_A_kernel<<<2048, 256>>>();
    scatter_kernel<<<(EE * F2) / 256, 256>>>(x, ei);

    // no_prop extractor on A (raw trace/total)
    zero_small_kernel<<<1, 128>>>();
    reduce_kernel<F2, false><<<256, 256>>>(0);
    extractor_kernel<<<1, 64>>>(np1_w, np1_b, np2_w, np3_w, F2, 1);

    for (int l = 0; l < LLAY; l++) {
        int insel  = (l == 0) ? 0 : ((l == 1) ? 1 : 2);
        int outsel = (l == 0) ? 1 : ((l == 1) ? 2 : 1);

        if (l == 0) {
            linear_kernel<32, true, false><<<PP / 128, 256>>>(insel, c0_m1w, c0_m1b, -1, 1);
            linear_kernel<32, true, false><<<PP / 128, 256>>>(insel, c0_m2w, c0_m2b, -1, 2);
        } else {
            // bn-adjusted weights from previous layer's finalize/adjust
            linear_kernel<64, true, false><<<PP / 128, 256>>>(insel, nullptr, nullptr, 1, 1);
            linear_kernel<64, true, false><<<PP / 128, 256>>>(insel, nullptr, nullptr, 2, 2);
        }

        bgemm_mma_kernel<<<dim3(4, 4, 64), 256, BGM_SMEM>>>();

        if (l == 0) linear_kernel<96,  false, true><<<PP / 128, 256>>>(insel, c0_m4w, c0_m4b, -1, outsel);
        else        linear_kernel<128, false, true><<<PP / 128, 256>>>(insel, nullptr, nullptr, 4, outsel);

        // stats + trace/total in one pass over pre-bn u
        zero_small_kernel<<<1, 128>>>();
        reduce_kernel<HH, true><<<256, 256>>>(outsel);
        finalize_kernel<<<1, 64>>>(bn_g + l * HH, bn_b + l * HH);
        extractor_kernel<<<1, 64>>>(fe1_w + (size_t)l * HFF * HH, fe1_b + (size_t)l * HFF,
                                    fe2_w + (size_t)l * HFF * HH, fe3_w + (size_t)l * HFF * HFF,
                                    HH, 0);
        if (l < LLAY - 1) {
            adjust_kernel<<<1, 64>>>(cm1_w + (size_t)l * HH * HH, cm1_b + (size_t)l * HH,
                                     cm2_w + (size_t)l * HH * HH, cm2_b + (size_t)l * HH,
                                     cm4_w + (size_t)l * HH * 2 * HH, cm4_b + (size_t)l * HH);
        }
    }

    final_kernel<<<1, 64>>>(ac_w, ac_b, fl_w, fl_b, (float*)d_out);
}

// round 9
// speedup vs baseline: 2.5799x; 1.3286x over previous
#include <cuda_runtime.h>
#include <cuda_bf16.h>
#include <math.h>
#include <stdint.h>

#define NN   512
#define PP   (NN*NN)
#define F2   32
#define HH   64
#define HFF  64
#define CCLS 10
#define LLAY 3
#define EE   16384
#define BN_EPS 1e-5f

// ---------------- scratch (static device memory; no allocations) ----------------
__device__ float g_A[(size_t)PP * F2];                 // adjacency fp32, channel-major [32][P]
__device__ __nv_bfloat16 g_Ah[(size_t)PP * F2], g_Al[(size_t)PP * F2];
__device__ __nv_bfloat16 g_uh0[(size_t)PP * HH], g_ul0[(size_t)PP * HH];
__device__ __nv_bfloat16 g_uh1[(size_t)PP * HH], g_ul1[(size_t)PP * HH];
__device__ __nv_bfloat16 g_o1h[(size_t)PP * HH], g_o1l[(size_t)PP * HH];
__device__ __nv_bfloat16 g_o2h[(size_t)PP * HH], g_o2l[(size_t)PP * HH];
__device__ __nv_bfloat16 g_mh [(size_t)PP * HH], g_ml [(size_t)PP * HH];  // mult splits
__device__ float g_stats[HH];                 // sumsq
__device__ float g_trace[HH];
__device__ float g_total[HH];                 // sum
__device__ float g_acc  [HFF];
__device__ float g_scale[HH], g_shift[HH];
__device__ float g_w1a[HH*HH], g_b1a[HH];
__device__ float g_w2a[HH*HH], g_b2a[HH];
__device__ float g_w4a[HH*2*HH], g_b4a[HH];

__device__ __forceinline__ const __nv_bfloat16* bufh(int s) {
    return (s == 0) ? g_Ah : (s == 1) ? g_uh0 : g_uh1;
}
__device__ __forceinline__ const __nv_bfloat16* bufl(int s) {
    return (s == 0) ? g_Al : (s == 1) ? g_ul0 : g_ul1;
}

// ---------------- PTX helpers (portable to compute_103) ----------------
__device__ __forceinline__ uint32_t smem_to_u32(const void* p) {
    uint32_t a;
    asm("{ .reg .u64 t; cvta.to.shared.u64 t, %1; cvt.u32.u64 %0, t; }" : "=r"(a) : "l"(p));
    return a;
}
#define CP_ASYNC16(dst, src) \
    asm volatile("cp.async.cg.shared.global [%0], [%1], 16;" :: "r"(dst), "l"(src))
#define CP_COMMIT() asm volatile("cp.async.commit_group;" ::: "memory")
#define CP_WAIT0()  asm volatile("cp.async.wait_group 0;" ::: "memory")
#define CP_WAIT1()  asm volatile("cp.async.wait_group 1;" ::: "memory")

__device__ __forceinline__ void ldmA(uint32_t* r, uint32_t addr) {
    asm volatile("ldmatrix.sync.aligned.m8n8.x4.shared.b16 {%0,%1,%2,%3}, [%4];"
        : "=r"(r[0]), "=r"(r[1]), "=r"(r[2]), "=r"(r[3]) : "r"(addr));
}
__device__ __forceinline__ void ldmBt(uint32_t* r, uint32_t addr) {
    asm volatile("ldmatrix.sync.aligned.m8n8.x2.trans.shared.b16 {%0,%1}, [%2];"
        : "=r"(r[0]), "=r"(r[1]) : "r"(addr));
}
__device__ __forceinline__ void mma16816(float* c, const uint32_t* a, const uint32_t* b) {
    asm volatile("mma.sync.aligned.m16n8k16.row.col.f32.bf16.bf16.f32 "
        "{%0,%1,%2,%3}, {%4,%5,%6,%7}, {%8,%9}, {%0,%1,%2,%3};"
        : "+f"(c[0]), "+f"(c[1]), "+f"(c[2]), "+f"(c[3])
        : "r"(a[0]), "r"(a[1]), "r"(a[2]), "r"(a[3]), "r"(b[0]), "r"(b[1]));
}
__device__ __forceinline__ void split_pair(float v0, float v1, uint32_t& hi, uint32_t& lo) {
    __nv_bfloat16 h0 = __float2bfloat16(v0), h1 = __float2bfloat16(v1);
    __nv_bfloat16 l0 = __float2bfloat16(v0 - __bfloat162float(h0));
    __nv_bfloat16 l1 = __float2bfloat16(v1 - __bfloat162float(h1));
    __nv_bfloat162 hp = __nv_bfloat162(h0, h1), lp = __nv_bfloat162(l0, l1);
    hi = *reinterpret_cast<uint32_t*>(&hp);
    lo = *reinterpret_cast<uint32_t*>(&lp);
}

// ---------------- small utility kernels ----------------
__global__ void zero_A_kernel() {
    size_t n4 = ((size_t)PP * F2) / 4;
    float4* p = reinterpret_cast<float4*>(g_A);
    for (size_t i = blockIdx.x * blockDim.x + threadIdx.x; i < n4;
         i += (size_t)gridDim.x * blockDim.x)
        p[i] = make_float4(0.f, 0.f, 0.f, 0.f);
}
__global__ void zero_small_kernel() {
    int t = threadIdx.x;
    if (t < HH) { g_stats[t] = 0.f; g_trace[t] = 0.f; g_total[t] = 0.f; }
}
// scatter into CHANNEL-major adjacency: g_A[c][src*512+dst]
__global__ void scatter_kernel(const float* __restrict__ x, const int* __restrict__ ei) {
    int t = blockIdx.x * blockDim.x + threadIdx.x;
    if (t >= EE * F2) return;
    int e = t >> 5;
    int c = t & 31;
    int src = ei[e];
    int dst = ei[EE + e];
    float v = (c < 16) ? x[src * 16 + c] : x[dst * 16 + (c - 16)];
    atomicAdd(&g_A[(size_t)c * PP + (size_t)src * NN + dst], v);
}

// convert A fp32 -> bf16 hi/lo splits; fused per-channel total/trace reduction
__global__ __launch_bounds__(256)
void convertA_kernel() {
    const int c = blockIdx.y;
    const float* src = g_A + (size_t)c * PP;
    __nv_bfloat16* dh = g_Ah + (size_t)c * PP;
    __nv_bfloat16* dl = g_Al + (size_t)c * PP;
    float s = 0.f, tr = 0.f;
    for (int p4 = blockIdx.x * 256 + threadIdx.x; p4 < PP / 4; p4 += gridDim.x * 256) {
        float4 v = *reinterpret_cast<const float4*>(src + p4 * 4);
        uint32_t h01, l01, h23, l23;
        split_pair(v.x, v.y, h01, l01);
        split_pair(v.z, v.w, h23, l23);
        uint2 hh = make_uint2(h01, h23), ll = make_uint2(l01, l23);
        *reinterpret_cast<uint2*>(dh + p4 * 4) = hh;
        *reinterpret_cast<uint2*>(dl + p4 * 4) = ll;
        s += v.x + v.y + v.z + v.w;
        int d = (4 * p4) % 513;
        if (d == 0)   tr += v.x;
        if (d == 512) tr += v.y;
        if (d == 511) tr += v.z;
        if (d == 510) tr += v.w;
    }
    __shared__ float ssum, strc;
    if (threadIdx.x == 0) { ssum = 0.f; strc = 0.f; }
    __syncthreads();
    for (int o = 16; o > 0; o >>= 1) {
        s  += __shfl_xor_sync(0xffffffff, s, o);
        tr += __shfl_xor_sync(0xffffffff, tr, o);
    }
    if ((threadIdx.x & 31) == 0) { atomicAdd(&ssum, s); atomicAdd(&strc, tr); }
    __syncthreads();
    if (threadIdx.x == 0) { atomicAdd(&g_total[c], ssum); atomicAdd(&g_trace[c], strc); }
}

// ---------------- fused m1+m2 tensor kernel ----------------
// C[128 out][P] = [W1;W2][128][K] @ X[K][P], bf16x3, writes o1/o2 hi/lo channel-major.
template <int K>
__global__ __launch_bounds__(256)
void m1m2_kernel(int insel, int wsel, const float* __restrict__ W1e,
                 const float* __restrict__ b1e, const float* __restrict__ W2e,
                 const float* __restrict__ b2e) {
    extern __shared__ char smem[];
    const uint32_t sb  = smem_to_u32(smem);
    const uint32_t sWh = sb, sWl = sb + 16384;
    const uint32_t sXh = sb + 32768, sXl = sXh + K * 256;
    float* sbias = reinterpret_cast<float*>(smem + 32768 + 2 * K * 256);
    const int tid = threadIdx.x;
    const int n0 = blockIdx.x * 128;

    const float* W1 = wsel ? g_w1a : W1e;
    const float* W2 = wsel ? g_w2a : W2e;
    const float* b1 = wsel ? g_b1a : b1e;
    const float* b2 = wsel ? g_b2a : b2e;

    // X tiles via cp.async (channel-major: contiguous in p)
    const __nv_bfloat16* Xh = bufh(insel);
    const __nv_bfloat16* Xl = bufl(insel);
#pragma unroll
    for (int it = 0; it < K * 32 / 256; it++) {
        int idx = tid + it * 256;
        int half = idx / (K * 16);
        int rem = idx % (K * 16);
        int k = rem >> 4, c = rem & 15;
        const __nv_bfloat16* src = (half ? Xl : Xh) + (size_t)k * PP + n0 + c * 8;
        uint32_t dst = (half ? sXl : sXh) + k * 256 + (((uint32_t)(c ^ (k & 7))) << 4);
        CP_ASYNC16(dst, (uint64_t)__cvta_generic_to_global(src));
    }
    CP_COMMIT();

    // W split into smem (rows padded to 128B)
    for (int i = tid; i < 128 * K; i += 256) {
        int m = i / K, k = i - m * K;
        float wv = (m < 64) ? W1[m * K + k] : W2[(m - 64) * K + k];
        __nv_bfloat16 h = __float2bfloat16(wv);
        __nv_bfloat16 l = __float2bfloat16(wv - __bfloat162float(h));
        uint32_t off = m * 128 + (((uint32_t)((k >> 3) ^ (m & 7))) << 4) + (k & 7) * 2;
        *reinterpret_cast<__nv_bfloat16*>(smem + off) = h;
        *reinterpret_cast<__nv_bfloat16*>(smem + 16384 + off) = l;
    }
    if (tid < 128) sbias[tid] = (tid < 64) ? b1[tid] : b2[tid - 64];

    CP_WAIT0();
    __syncthreads();

    const int lane = tid & 31, w = tid >> 5;
    const int wm = w & 1, wn = w >> 1;
    const int m0w = wm * 64, n0w = wn * 32;
    const int a_row_lane = (lane & 7) + ((lane >> 3) & 1) * 8;
    const int a_k_lane = lane >> 4;
    const int b_k_lane = lane & 15;

    float acc[4][4][4];
#pragma unroll
    for (int i = 0; i < 4; i++)
#pragma unroll
        for (int j = 0; j < 4; j++)
#pragma unroll
            for (int q = 0; q < 4; q++) acc[i][j][q] = 0.f;

#pragma unroll
    for (int ks = 0; ks < K / 16; ks++) {
        uint32_t Ah[4][4], Al[4][4], Bh[4][2], Bl[4][2];
#pragma unroll
        for (int mt = 0; mt < 4; mt++) {
            int row = m0w + mt * 16 + a_row_lane;
            uint32_t chunk = (uint32_t)((ks * 2 + a_k_lane) ^ (row & 7));
            uint32_t off = row * 128 + (chunk << 4);
            ldmA(Ah[mt], sWh + off);
            ldmA(Al[mt], sWl + off);
        }
        {
            int kk = ks * 16 + b_k_lane;
#pragma unroll
            for (int nt = 0; nt < 4; nt++) {
                uint32_t off = kk * 256 + (((uint32_t)((wn * 4 + nt) ^ (kk & 7))) << 4);
                ldmBt(Bh[nt], sXh + off);
                ldmBt(Bl[nt], sXl + off);
            }
        }
#pragma unroll
        for (int mt = 0; mt < 4; mt++)
#pragma unroll
            for (int nt = 0; nt < 4; nt++) {
                mma16816(acc[mt][nt], Ah[mt], Bh[nt]);
                mma16816(acc[mt][nt], Ah[mt], Bl[nt]);
                mma16816(acc[mt][nt], Al[mt], Bh[nt]);
            }
    }

    // epilogue: channel-major bf16 hi/lo
    const int rq = lane >> 2, cq = (lane & 3) * 2;
    __nv_bfloat16* OH = wm ? g_o2h : g_o1h;
    __nv_bfloat16* OL = wm ? g_o2l : g_o1l;
#pragma unroll
    for (int mt = 0; mt < 4; mt++) {
#pragma unroll
        for (int nt = 0; nt < 4; nt++) {
            size_t p = (size_t)(n0 + n0w + nt * 8 + cq);
#pragma unroll
            for (int half = 0; half < 2; half++) {
                int rloc = mt * 16 + rq + 8 * half;   // local channel 0..63
                float bv = sbias[m0w + rloc];
                float v0 = acc[mt][nt][2 * half] + bv;
                float v1 = acc[mt][nt][2 * half + 1] + bv;
                uint32_t hi, lo;
                split_pair(v0, v1, hi, lo);
                *reinterpret_cast<uint32_t*>(OH + (size_t)rloc * PP + p) = hi;
                *reinterpret_cast<uint32_t*>(OL + (size_t)rloc * PP + p) = lo;
            }
        }
    }
}

// ---------------- m4 tensor kernel + fused reduce ----------------
// u_next[64][P] = W4[64][K] @ concat(mult, u)[K][P]; K = 64 + CIN2.
template <int CIN2, bool WRITE>
__global__ __launch_bounds__(256)
void m4_kernel(int insel, int wsel, int outsel,
               const float* __restrict__ W4e, const float* __restrict__ b4e) {
    constexpr int K = 64 + CIN2;
    extern __shared__ char smem[];
    const uint32_t sb  = smem_to_u32(smem);
    const uint32_t sWh = sb, sWl = sb + 16384;
    const uint32_t sXh = sb + 32768, sXl = sXh + K * 256;
    float* sbias = reinterpret_cast<float*>(smem + 32768 + 2 * K * 256);
    float* s_sum = sbias + 64;
    float* s_sq  = s_sum + 64;
    float* s_tr  = s_sq + 64;
    const int tid = threadIdx.x;
    const int n0 = blockIdx.x * 128;

    const float* W4 = wsel ? g_w4a : W4e;
    const float* b4 = wsel ? g_b4a : b4e;

    const __nv_bfloat16* Uh = bufh(insel);
    const __nv_bfloat16* Ul = bufl(insel);
#pragma unroll
    for (int it = 0; it < K * 32 / 256; it++) {
        int idx = tid + it * 256;
        int half = idx / (K * 16);
        int rem = idx % (K * 16);
        int k = rem >> 4, c = rem & 15;
        const __nv_bfloat16* src;
        if (k < 64) src = (half ? g_ml : g_mh) + (size_t)k * PP + n0 + c * 8;
        else        src = (half ? Ul : Uh) + (size_t)(k - 64) * PP + n0 + c * 8;
        uint32_t dst = (half ? sXl : sXh) + k * 256 + (((uint32_t)(c ^ (k & 7))) << 4);
        CP_ASYNC16(dst, (uint64_t)__cvta_generic_to_global(src));
    }
    CP_COMMIT();

    for (int i = tid; i < 64 * K; i += 256) {
        int m = i / K, k = i - m * K;
        float wv = W4[m * K + k];
        __nv_bfloat16 h = __float2bfloat16(wv);
        __nv_bfloat16 l = __float2bfloat16(wv - __bfloat162float(h));
        uint32_t off = m * 256 + (((uint32_t)((k >> 3) ^ (m & 7))) << 4) + (k & 7) * 2;
        *reinterpret_cast<__nv_bfloat16*>(smem + off) = h;
        *reinterpret_cast<__nv_bfloat16*>(smem + 16384 + off) = l;
    }
    if (tid < 64) { sbias[tid] = b4[tid]; s_sum[tid] = 0.f; s_sq[tid] = 0.f; s_tr[tid] = 0.f; }

    CP_WAIT0();
    __syncthreads();

    const int lane = tid & 31, w = tid >> 5;
    const int wm = w & 1, wn = w >> 1;
    const int m0w = wm * 32, n0w = wn * 32;
    const int a_row_lane = (lane & 7) + ((lane >> 3) & 1) * 8;
    const int a_k_lane = lane >> 4;
    const int b_k_lane = lane & 15;

    float acc[2][4][4];
#pragma unroll
    for (int i = 0; i < 2; i++)
#pragma unroll
        for (int j = 0; j < 4; j++)
#pragma unroll
            for (int q = 0; q < 4; q++) acc[i][j][q] = 0.f;

#pragma unroll
    for (int ks = 0; ks < K / 16; ks++) {
        uint32_t Ah[2][4], Al[2][4], Bh[4][2], Bl[4][2];
#pragma unroll
        for (int mt = 0; mt < 2; mt++) {
            int row = m0w + mt * 16 + a_row_lane;
            uint32_t chunk = (uint32_t)((ks * 2 + a_k_lane) ^ (row & 7));
            uint32_t off = row * 256 + (chunk << 4);
            ldmA(Ah[mt], sWh + off);
            ldmA(Al[mt], sWl + off);
        }
        {
            int kk = ks * 16 + b_k_lane;
#pragma unroll
            for (int nt = 0; nt < 4; nt++) {
                uint32_t off = kk * 256 + (((uint32_t)((wn * 4 + nt) ^ (kk & 7))) << 4);
                ldmBt(Bh[nt], sXh + off);
                ldmBt(Bl[nt], sXl + off);
            }
        }
#pragma unroll
        for (int mt = 0; mt < 2; mt++)
#pragma unroll
            for (int nt = 0; nt < 4; nt++) {
                mma16816(acc[mt][nt], Ah[mt], Bh[nt]);
                mma16816(acc[mt][nt], Ah[mt], Bl[nt]);
                mma16816(acc[mt][nt], Al[mt], Bh[nt]);
            }
    }

    // epilogue: optional split-write + fused sum/sumsq/trace
    const int rq = lane >> 2, cq = (lane & 3) * 2;
    __nv_bfloat16* UOH = (outsel == 1) ? g_uh0 : g_uh1;
    __nv_bfloat16* UOL = (outsel == 1) ? g_ul0 : g_ul1;
    float rsum[2][2] = {{0.f, 0.f}, {0.f, 0.f}};
    float rsq [2][2] = {{0.f, 0.f}, {0.f, 0.f}};
#pragma unroll
    for (int mt = 0; mt < 2; mt++) {
#pragma unroll
        for (int nt = 0; nt < 4; nt++) {
            int p = n0 + n0w + nt * 8 + cq;
#pragma unroll
            for (int half = 0; half < 2; half++) {
                int rloc = m0w + mt * 16 + rq + 8 * half;   // 0..63
                float bv = sbias[rloc];
                float v0 = acc[mt][nt][2 * half] + bv;
                float v1 = acc[mt][nt][2 * half + 1] + bv;
                if (WRITE) {
                    uint32_t hi, lo;
                    split_pair(v0, v1, hi, lo);
                    *reinterpret_cast<uint32_t*>(UOH + (size_t)rloc * PP + p) = hi;
                    *reinterpret_cast<uint32_t*>(UOL + (size_t)rloc * PP + p) = lo;
                }
                rsum[mt][half] += v0 + v1;
                rsq [mt][half] += v0 * v0 + v1 * v1;
                if (p % 513 == 0)       atomicAdd(&s_tr[rloc], v0);
                if ((p + 1) % 513 == 0) atomicAdd(&s_tr[rloc], v1);
            }
        }
    }
#pragma unroll
    for (int mt = 0; mt < 2; mt++)
#pragma unroll
        for (int half = 0; half < 2; half++) {
            float s = rsum[mt][half], q = rsq[mt][half];
            s += __shfl_xor_sync(0xffffffff, s, 1);
            s += __shfl_xor_sync(0xffffffff, s, 2);
            q += __shfl_xor_sync(0xffffffff, q, 1);
            q += __shfl_xor_sync(0xffffffff, q, 2);
            if ((lane & 3) == 0) {
                int rloc = m0w + mt * 16 + rq + 8 * half;
                atomicAdd(&s_sum[rloc], s);
                atomicAdd(&s_sq[rloc], q);
            }
        }
    __syncthreads();
    if (tid < 64) {
        atomicAdd(&g_total[tid], s_sum[tid]);
        atomicAdd(&g_stats[tid], s_sq[tid]);
        atomicAdd(&g_trace[tid], s_tr[tid]);
    }
}

// ---------------- mma.sync batched GEMM: mult[h] = o1[h] @ o2[h] (bf16x3) ----------------
#define BGM_STAGE 65536
#define BGM_SMEM  (2 * BGM_STAGE)

__device__ __forceinline__ void bgm_load_stage(int k0, uint32_t sb, int h, int m0, int n0) {
    const int tid = threadIdx.x;
    const size_t hoff = (size_t)h << 18;
#pragma unroll
    for (int it = 0; it < 8; it++) {
        int idx = tid + it * 256;
        int half = idx >> 10;
        int r = (idx >> 3) & 127;
        int c = idx & 7;
        const __nv_bfloat16* src = (half ? g_o1l : g_o1h) + hoff + (size_t)(m0 + r) * NN + k0 + c * 8;
        uint32_t dst = sb + half * 16384 + r * 128 + (((uint32_t)(c ^ (r & 7))) << 4);
        CP_ASYNC16(dst, (uint64_t)__cvta_generic_to_global(src));
    }
#pragma unroll
    for (int it = 0; it < 8; it++) {
        int idx = tid + it * 256;
        int half = idx >> 10;
        int k = (idx >> 4) & 63;
        int c = idx & 15;
        const __nv_bfloat16* src = (half ? g_o2l : g_o2h) + hoff + (size_t)(k0 + k) * NN + n0 + c * 8;
        uint32_t dst = sb + 32768 + half * 16384 + k * 256 + (((uint32_t)(c ^ (k & 7))) << 4);
        CP_ASYNC16(dst, (uint64_t)__cvta_generic_to_global(src));
    }
}

__global__ __launch_bounds__(256, 1)
void bgemm_mma_kernel() {
    extern __shared__ char smem[];
    const uint32_t sbase = smem_to_u32(smem);
    const int tid = threadIdx.x;
    const int lane = tid & 31;
    const int w = tid >> 5;
    const int wm = w & 1;
    const int wn = w >> 1;
    const int m0w = wm * 64;
    const int n0w = wn * 32;
    const int h  = blockIdx.z;
    const int m0 = blockIdx.y * 128;
    const int n0 = blockIdx.x * 128;

    const int a_row_lane = (lane & 7) + ((lane >> 3) & 1) * 8;
    const int a_k_lane   = lane >> 4;
    const int b_k_lane   = lane & 15;

    float acc[4][4][4];
#pragma unroll
    for (int i = 0; i < 4; i++)
#pragma unroll
        for (int j = 0; j < 4; j++)
#pragma unroll
            for (int q = 0; q < 4; q++) acc[i][j][q] = 0.f;

    bgm_load_stage(0, sbase, h, m0, n0);
    CP_COMMIT();

    const int NK = NN / 64;  // 8
    for (int kc = 0; kc < NK; kc++) {
        if (kc + 1 < NK) {
            bgm_load_stage((kc + 1) * 64, sbase + ((kc + 1) & 1) * BGM_STAGE, h, m0, n0);
            CP_COMMIT();
            CP_WAIT1();
        } else {
            CP_WAIT0();
        }
        __syncthreads();

        const uint32_t sA = sbase + (kc & 1) * BGM_STAGE;
        const uint32_t sB = sA + 32768;
#pragma unroll
        for (int ks = 0; ks < 4; ks++) {
            uint32_t Ah[4][4], Al[4][4], Bh[4][2], Bl[4][2];
#pragma unroll
            for (int mt = 0; mt < 4; mt++) {
                int row = m0w + mt * 16 + a_row_lane;
                int kchunk = ks * 2 + a_k_lane;
                uint32_t off = row * 128 + (((uint32_t)(kchunk ^ (row & 7))) << 4);
                ldmA(Ah[mt], sA + off);
                ldmA(Al[mt], sA + 16384 + off);
            }
            {
                int kk = ks * 16 + b_k_lane;
                int kx = kk & 7;
#pragma unroll
                for (int nt = 0; nt < 4; nt++) {
                    int nchunk = wn * 4 + nt;
                    uint32_t off = kk * 256 + (((uint32_t)(nchunk ^ kx)) << 4);
                    ldmBt(Bh[nt], sB + off);
                    ldmBt(Bl[nt], sB + 16384 + off);
                }
            }
#pragma unroll
            for (int mt = 0; mt < 4; mt++)
#pragma unroll
                for (int nt = 0; nt < 4; nt++) {
                    mma16816(acc[mt][nt], Ah[mt], Bh[nt]);
                    mma16816(acc[mt][nt], Ah[mt], Bl[nt]);
                    mma16816(acc[mt][nt], Al[mt], Bh[nt]);
                }
        }
        __syncthreads();
    }

    // epilogue: write mult as bf16 hi/lo channel-major
    __nv_bfloat16* mh = g_mh + ((size_t)h << 18);
    __nv_bfloat16* ml = g_ml + ((size_t)h << 18);
    const int rq = lane >> 2;
    const int cq = (lane & 3) * 2;
#pragma unroll
    for (int mt = 0; mt < 4; mt++) {
#pragma unroll
        for (int nt = 0; nt < 4; nt++) {
            int row = m0 + m0w + mt * 16 + rq;
            int col = n0 + n0w + nt * 8 + cq;
            uint32_t hi0, lo0, hi1, lo1;
            split_pair(acc[mt][nt][0], acc[mt][nt][1], hi0, lo0);
            split_pair(acc[mt][nt][2], acc[mt][nt][3], hi1, lo1);
            size_t off0 = (size_t)row * NN + col;
            size_t off1 = (size_t)(row + 8) * NN + col;
            *reinterpret_cast<uint32_t*>(mh + off0) = hi0;
            *reinterpret_cast<uint32_t*>(ml + off0) = lo0;
            *reinterpret_cast<uint32_t*>(mh + off1) = hi1;
            *reinterpret_cast<uint32_t*>(ml + off1) = lo1;
        }
    }
}

// ---------------- bn finalize / weight folding / extractor / head ----------------
__global__ void finalize_kernel(const float* __restrict__ g, const float* __restrict__ b) {
    int c = threadIdx.x;  // 64
    float sum = g_total[c], sumsq = g_stats[c], tr = g_trace[c];
    float m = sum * (1.f / (float)PP);
    float var = sumsq * (1.f / (float)PP) - m * m;
    float sc = g[c] * rsqrtf(var + BN_EPS);
    float sh = b[c] - m * sc;
    g_scale[c] = sc;
    g_shift[c] = sh;
    g_trace[c] = tr * sc + sh * (float)NN;
    g_total[c] = sum * sc + sh * (float)PP;
}

__global__ void adjust_kernel(const float* __restrict__ w1, const float* __restrict__ b1,
                              const float* __restrict__ w2, const float* __restrict__ b2,
                              const float* __restrict__ w4, const float* __restrict__ b4) {
    int o = threadIdx.x;  // 64
    float a1 = b1[o], a2 = b2[o], a4 = b4[o];
    for (int c = 0; c < HH; c++) {
        float sc = g_scale[c], sh = g_shift[c];
        float w = w1[o * HH + c];
        g_w1a[o * HH + c] = w * sc; a1 += w * sh;
        w = w2[o * HH + c];
        g_w2a[o * HH + c] = w * sc; a2 += w * sh;
        g_w4a[o * 2 * HH + c] = w4[o * 2 * HH + c];
        w = w4[o * 2 * HH + HH + c];
        g_w4a[o * 2 * HH + HH + c] = w * sc; a4 += w * sh;
    }
    g_b1a[o] = a1; g_b2a[o] = a2; g_b4a[o] = a4;
}

__global__ void extractor_kernel(const float* __restrict__ w1, const float* __restrict__ b1,
                                 const float* __restrict__ w2, const float* __restrict__ w3,
                                 int cin, int init) {
    __shared__ float s_out[HFF];
    int o = threadIdx.x;  // 64
    const float inv_n = 1.f / (float)NN;
    const float inv_od = 1.f / ((float)NN * (float)(NN - 1));
    float v = b1[o];
    for (int c = 0; c < cin; c++) {
        v += (g_trace[c] * inv_n) * w1[o * cin + c];
        v += ((g_total[c] - g_trace[c]) * inv_od) * w2[o * cin + c];
    }
    s_out[o] = v;
    __syncthreads();
    float t = 0.f;
    for (int j = 0; j < HFF; j++) t += fmaxf(s_out[j], 0.f) * w3[o * HFF + j];
    v += t;
    if (init) g_acc[o] = v;
    else      g_acc[o] += v;
}

__global__ void final_kernel(const float* __restrict__ acw, const float* __restrict__ acb,
                             const float* __restrict__ flw, const float* __restrict__ flb,
                             float* __restrict__ out) {
    __shared__ float t[HFF], h2[HFF], lg[CCLS];
    int o = threadIdx.x;
    t[o] = fmaxf(g_acc[o], 0.f) * (1.f / (float)LLAY);
    __syncthreads();
    float v = acb[o];
    for (int j = 0; j < HFF; j++) v += t[j] * acw[o * HFF + j];
    h2[o] = t[o] + fmaxf(v, 0.f);
    __syncthreads();
    if (o < CCLS) {
        float s = flb[o];
        for (int j = 0; j < HFF; j++) s += h2[j] * flw[o * HFF + j];
        lg[o] = s;
    }
    __syncthreads();
    if (o < CCLS) {
        float m = -1e30f;
        for (int j = 0; j < CCLS; j++) m = fmaxf(m, lg[j]);
        float se = 0.f;
        for (int j = 0; j < CCLS; j++) se += expf(lg[j] - m);
        out[o] = lg[o] - m - logf(se);
    }
}

// ---------------- launcher ----------------
extern "C" void kernel_launch(void* const* d_in, const int* in_sizes, int n_in,
                              void* d_out, int out_size) {
    const float* x      = (const float*)d_in[0];
    const int*   ei     = (const int*)  d_in[1];
    const float* np1_w  = (const float*)d_in[2];
    const float* np1_b  = (const float*)d_in[3];
    const float* np2_w  = (const float*)d_in[4];
    const float* np3_w  = (const float*)d_in[5];
    const float* c0_m1w = (const float*)d_in[6];
    const float* c0_m1b = (const float*)d_in[7];
    const float* c0_m2w = (const float*)d_in[8];
    const float* c0_m2b = (const float*)d_in[9];
    const float* c0_m4w = (const float*)d_in[10];
    const float* c0_m4b = (const float*)d_in[11];
    const float* cm1_w  = (const float*)d_in[12];
    const float* cm1_b  = (const float*)d_in[13];
    const float* cm2_w  = (const float*)d_in[14];
    const float* cm2_b  = (const float*)d_in[15];
    const float* cm4_w  = (const float*)d_in[16];
    const float* cm4_b  = (const float*)d_in[17];
    const float* bn_g   = (const float*)d_in[18];
    const float* bn_b   = (const float*)d_in[19];
    const float* fe1_w  = (const float*)d_in[20];
    const float* fe1_b  = (const float*)d_in[21];
    const float* fe2_w  = (const float*)d_in[22];
    const float* fe3_w  = (const float*)d_in[23];
    const float* ac_w   = (const float*)d_in[24];
    const float* ac_b   = (const float*)d_in[25];
    const float* fl_w   = (const float*)d_in[26];
    const float* fl_b   = (const float*)d_in[27];

    const int SM_M12_64 = 32768 + 2 * 64 * 256 + 512;   // 66048
    const int SM_M12_32 = 32768 + 2 * 32 * 256 + 512;   // 49664
    const int SM_M4_128 = 32768 + 2 * 128 * 256 + 1024; // 99328
    const int SM_M4_96  = 32768 + 2 * 96 * 256 + 1024;  // 82944

    cudaFuncSetAttribute(bgemm_mma_kernel, cudaFuncAttributeMaxDynamicSharedMemorySize, BGM_SMEM);
    cudaFuncSetAttribute(m1m2_kernel<64>, cudaFuncAttributeMaxDynamicSharedMemorySize, SM_M12_64);
    cudaFuncSetAttribute(m1m2_kernel<32>, cudaFuncAttributeMaxDynamicSharedMemorySize, SM_M12_32);
    cudaFuncSetAttribute(m4_kernel<64, true>,  cudaFuncAttributeMaxDynamicSharedMemorySize, SM_M4_128);
    cudaFuncSetAttribute(m4_kernel<64, false>, cudaFuncAttributeMaxDynamicSharedMemorySize, SM_M4_128);
    cudaFuncSetAttribute(m4_kernel<32, true>,  cudaFuncAttributeMaxDynamicSharedMemorySize, SM_M4_96);

    // Build dense adjacency (channel-major) + splits + no_prop reduce
    zero_A_kernel<<<2048, 256>>>();
    scatter_kernel<<<(EE * F2) / 256, 256>>>(x, ei);
    zero_small_kernel<<<1, 128>>>();
    convertA_kernel<<<dim3(64, F2), 256>>>();
    extractor_kernel<<<1, 64>>>(np1_w, np1_b, np2_w, np3_w, F2, 1);

    for (int l = 0; l < LLAY; l++) {
        int insel  = (l == 0) ? 0 : ((l == 1) ? 1 : 2);
        int outsel = (l == 0) ? 1 : ((l == 1) ? 2 : 1);

        if (l == 0)
            m1m2_kernel<32><<<PP / 128, 256, SM_M12_32>>>(insel, 0, c0_m1w, c0_m1b, c0_m2w, c0_m2b);
        else
            m1m2_kernel<64><<<PP / 128, 256, SM_M12_64>>>(insel, 1, nullptr, nullptr, nullptr, nullptr);

        bgemm_mma_kernel<<<dim3(4, 4, 64), 256, BGM_SMEM>>>();

        zero_small_kernel<<<1, 128>>>();
        if (l == 0)
            m4_kernel<32, true><<<PP / 128, 256, SM_M4_96>>>(insel, 0, outsel, c0_m4w, c0_m4b);
        else if (l == 1)
            m4_kernel<64, true><<<PP / 128, 256, SM_M4_128>>>(insel, 1, outsel, nullptr, nullptr);
        else
            m4_kernel<64, false><<<PP / 128, 256, SM_M4_128>>>(insel, 1, outsel, nullptr, nullptr);

        finalize_kernel<<<1, 64>>>(bn_g + l * HH, bn_b + l * HH);
        extractor_kernel<<<1, 64>>>(fe1_w + (size_t)l * HFF * HH, fe1_b + (size_t)l * HFF,
                                    fe2_w + (size_t)l * HFF * HH, fe3_w + (size_t)l * HFF * HFF,
                                    HH, 0);
        if (l < LLAY - 1) {
            adjust_kernel<<<1, 64>>>(cm1_w + (size_t)l * HH * HH, cm1_b + (size_t)l * HH,
                                     cm2_w + (size_t)l * HH * HH, cm2_b + (size_t)l * HH,
                                     cm4_w + (size_t)l * HH * 2 * HH, cm4_b + (size_t)l * HH);
        }
    }

    final_kernel<<<1, 64>>>(ac_w, ac_b, fl_w, fl_b, (float*)d_out);
}